// round 12
// baseline (speedup 1.0000x reference)
#include <cuda_runtime.h>
#include <math.h>

// Problem constants
#define BATCH   8
#define SEQ     4096
#define M_TOTAL (BATCH * SEQ)   // 32768
#define NCODES  1024
#define KDIM    256
#define TOPM    3

// GEMM tiling
#define BM 128
#define BN 128
#define BK 16
#define NTILES (NCODES / BN)    // 8
#define MTILES (M_TOTAL / BM)   // 256

// Per-(row, n-tile) max of sim (1 MB) + per-m-tile completion counters
__device__ float g_rowmax[(size_t)M_TOTAL * NTILES];
__device__ int   g_cnt[MTILES];

// ---------------------------------------------------------------------------
// Packed fp32x2 helpers (bit-exact vs two fmaf)
// ---------------------------------------------------------------------------
__device__ __forceinline__ unsigned long long pack2(float x) {
    unsigned long long r;
    asm("mov.b64 %0, {%1, %1};" : "=l"(r) : "f"(x));
    return r;
}
__device__ __forceinline__ void fma2(unsigned long long& acc,
                                     unsigned long long a,
                                     unsigned long long b) {
    asm("fma.rn.f32x2 %0, %1, %2, %0;" : "+l"(acc) : "l"(a), "l"(b));
}
__device__ __forceinline__ float2 unpack2(unsigned long long v) {
    float2 f;
    asm("mov.b64 {%0, %1}, %2;" : "=f"(f.x), "=f"(f.y) : "l"(v));
    return f;
}

// ---------------------------------------------------------------------------
// Counter reset (graph replays reuse device globals -> must rezero each launch)
// ---------------------------------------------------------------------------
__global__ void vq_zero_cnt_kernel() { g_cnt[threadIdx.x] = 0; }

// ---------------------------------------------------------------------------
// Fused kernel: FFMA2 GEMM (unchanged R11 mainloop+epilogue) + last-arriver
// per-m-tile top-3 + Gumbel softmax. The 8 CTAs sharing blockIdx.y bump
// g_cnt[y]; the 8th runs the topk for rows [y*128, y*128+128) reading the
// just-written sim tiles from L2.
// ---------------------------------------------------------------------------
__global__ __launch_bounds__(256, 2)
void vq_fused_kernel(const float* __restrict__ A,    // [M_TOTAL, KDIM]
                     const float* __restrict__ Bm,   // [NCODES,  KDIM]
                     float* __restrict__ C,          // [M_TOTAL, NCODES]
                     const int*   __restrict__ mask, // [M_TOTAL]
                     const float* __restrict__ u,    // [M_TOTAL, 3]
                     float* __restrict__ out_idx,    // [M_TOTAL, 3]
                     float* __restrict__ out_w)      // [M_TOTAL, 3]
{
    __shared__ float As[BK][BM + 4];   // stride 132 floats
    __shared__ float Bs[BK][BN + 4];
    __shared__ int s_last;

    const int bn0 = blockIdx.x * BN;
    const int bm0 = blockIdx.y * BM;
    const int tid = threadIdx.x;
    const int tx  = tid & 15;          // 0..15 -> N
    const int ty  = tid >> 4;          // 0..15 -> M

    const int lrow0 = tid >> 2;              // 0..63
    const int lrow1 = lrow0 + 64;            // 64..127
    const int lc4   = (tid & 3) * 4;         // 0,4,8,12

    const float* Aptr0 = &A[(size_t)(bm0 + lrow0) * KDIM + lc4];
    const float* Aptr1 = &A[(size_t)(bm0 + lrow1) * KDIM + lc4];
    const float* Bptr0 = &Bm[(size_t)(bn0 + lrow0) * KDIM + lc4];
    const float* Bptr1 = &Bm[(size_t)(bn0 + lrow1) * KDIM + lc4];

    unsigned long long acc2[8][4];
#pragma unroll
    for (int i = 0; i < 8; i++)
#pragma unroll
        for (int j = 0; j < 4; j++) acc2[i][j] = 0ull;

    // Prologue: load chunk 0
    float4 pa0 = *reinterpret_cast<const float4*>(Aptr0);
    float4 pa1 = *reinterpret_cast<const float4*>(Aptr1);
    float4 pb0 = *reinterpret_cast<const float4*>(Bptr0);
    float4 pb1 = *reinterpret_cast<const float4*>(Bptr1);

#pragma unroll 1
    for (int c = 0; c < KDIM / BK; c++) {
        As[lc4 + 0][lrow0] = pa0.x; As[lc4 + 1][lrow0] = pa0.y;
        As[lc4 + 2][lrow0] = pa0.z; As[lc4 + 3][lrow0] = pa0.w;
        As[lc4 + 0][lrow1] = pa1.x; As[lc4 + 1][lrow1] = pa1.y;
        As[lc4 + 2][lrow1] = pa1.z; As[lc4 + 3][lrow1] = pa1.w;
        Bs[lc4 + 0][lrow0] = pb0.x; Bs[lc4 + 1][lrow0] = pb0.y;
        Bs[lc4 + 2][lrow0] = pb0.z; Bs[lc4 + 3][lrow0] = pb0.w;
        Bs[lc4 + 0][lrow1] = pb1.x; Bs[lc4 + 1][lrow1] = pb1.y;
        Bs[lc4 + 2][lrow1] = pb1.z; Bs[lc4 + 3][lrow1] = pb1.w;
        __syncthreads();

        if (c + 1 < KDIM / BK) {
            int koff = (c + 1) * BK;
            pa0 = *reinterpret_cast<const float4*>(Aptr0 + koff);
            pa1 = *reinterpret_cast<const float4*>(Aptr1 + koff);
            pb0 = *reinterpret_cast<const float4*>(Bptr0 + koff);
            pb1 = *reinterpret_cast<const float4*>(Bptr1 + koff);
        }

#pragma unroll
        for (int kk = 0; kk < BK; kk++) {
            float4 a0 = *reinterpret_cast<const float4*>(&As[kk][ty * 4]);
            float4 a1 = *reinterpret_cast<const float4*>(&As[kk][64 + ty * 4]);
            ulonglong2 bp = *reinterpret_cast<const ulonglong2*>(&Bs[kk][tx * 4]);
            ulonglong2 bq = *reinterpret_cast<const ulonglong2*>(&Bs[kk][64 + tx * 4]);

            float av[8] = {a0.x, a0.y, a0.z, a0.w, a1.x, a1.y, a1.z, a1.w};
#pragma unroll
            for (int i = 0; i < 8; i++) {
                unsigned long long ap = pack2(av[i]);
                fma2(acc2[i][0], ap, bp.x);
                fma2(acc2[i][1], ap, bp.y);
                fma2(acc2[i][2], ap, bq.x);
                fma2(acc2[i][3], ap, bq.y);
            }
        }
        __syncthreads();
    }

    // ---- Store sim tile + per-(row,tile) max ----
#pragma unroll
    for (int ih = 0; ih < 2; ih++) {
#pragma unroll
        for (int ii = 0; ii < 4; ii++) {
            int i = ih * 4 + ii;
            int row = bm0 + ih * 64 + ty * 4 + ii;
            float* crow = &C[(size_t)row * NCODES + bn0];
            float2 c0 = unpack2(acc2[i][0]);
            float2 c1 = unpack2(acc2[i][1]);
            float2 c2 = unpack2(acc2[i][2]);
            float2 c3 = unpack2(acc2[i][3]);
            *reinterpret_cast<float4*>(&crow[tx * 4]) =
                make_float4(c0.x, c0.y, c1.x, c1.y);
            *reinterpret_cast<float4*>(&crow[64 + tx * 4]) =
                make_float4(c2.x, c2.y, c3.x, c3.y);

            float mrow = fmaxf(fmaxf(fmaxf(c0.x, c0.y), fmaxf(c1.x, c1.y)),
                               fmaxf(fmaxf(c2.x, c2.y), fmaxf(c3.x, c3.y)));
#pragma unroll
            for (int off = 1; off <= 8; off <<= 1)
                mrow = fmaxf(mrow, __shfl_xor_sync(0xffffffffu, mrow, off));
            if (tx == 0)
                g_rowmax[(size_t)row * NTILES + blockIdx.x] = mrow;
        }
    }

    // ---- Release this CTA's writes, bump completion counter ----
    __threadfence();        // each thread orders its own global stores
    __syncthreads();        // all fences precede the single atomic
    if (tid == 0) {
        int old = atomicAdd(&g_cnt[blockIdx.y], 1);
        s_last = (old == 7);
    }
    __syncthreads();
    if (!s_last) return;
    __threadfence();        // acquire: observe all 8 CTAs' tiles + rowmax

    // ---- Last arriver: top-3 + Gumbel softmax for rows [bm0, bm0+128) ----
    const int wid  = tid >> 5;
    const int lane = tid & 31;
    const float NEG_INF = -__int_as_float(0x7f800000);

#pragma unroll 1
    for (int r = 0; r < 16; r++) {
        const int row = bm0 + wid * 16 + r;
        const float* srow = C + (size_t)row * NCODES;

        // Tile selection: keep tiles whose max has <=2 strictly greater peers
        float x = g_rowmax[(size_t)row * NTILES + (lane & 7)];
        int cnt = 0;
#pragma unroll
        for (int j = 0; j < 8; j++) {
            float xj = __shfl_sync(0xffffffffu, x, j);
            cnt += (xj > x) ? 1 : 0;
        }
        unsigned keep = __ballot_sync(0xffffffffu, cnt <= 2) & 0xffu;

        float v0 = NEG_INF, v1 = NEG_INF, v2 = NEG_INF;
        int   i0 = 0x7fffffff, i1 = 0x7fffffff, i2 = 0x7fffffff;

#pragma unroll
        for (int t = 0; t < NTILES; t++) {
            if (keep & (1u << t)) {    // warp-uniform branch
                int base = t * 128 + lane * 4;
                float4 v4 = *reinterpret_cast<const float4*>(&srow[base]);
                float vv[4] = {v4.x, v4.y, v4.z, v4.w};
#pragma unroll
                for (int e = 0; e < 4; e++) {
                    float v = vv[e];
                    int idx = base + e;
                    if (v > v0)      { v2 = v1; i2 = i1; v1 = v0; i1 = i0; v0 = v; i0 = idx; }
                    else if (v > v1) { v2 = v1; i2 = i1; v1 = v;  i1 = idx; }
                    else if (v > v2) { v2 = v;  i2 = idx; }
                }
            }
        }

        // Warp merge with smaller-index tiebreak
        float lv[3] = {v0, v1, v2};
        int   li[3] = {i0, i1, i2};
        float tv[3];
        int   ti[3];
        int p = 0;
#pragma unroll
        for (int rr = 0; rr < 3; rr++) {
            float bv = (p < 3) ? lv[p] : NEG_INF;
            int   bi = (p < 3) ? li[p] : 0x7fffffff;
#pragma unroll
            for (int off = 16; off > 0; off >>= 1) {
                float ov = __shfl_xor_sync(0xffffffffu, bv, off);
                int   oi = __shfl_xor_sync(0xffffffffu, bi, off);
                if (ov > bv || (ov == bv && oi < bi)) { bv = ov; bi = oi; }
            }
            tv[rr] = bv; ti[rr] = bi;
            if (p < 3 && li[p] == bi) p++;
        }

        if (lane == 0) {
            int m = mask[row];
            if (m == 0) {
#pragma unroll
                for (int rr = 0; rr < 3; rr++) {
                    out_idx[row * 3 + rr] = (float)rr;
                    out_w[row * 3 + rr]   = 0.0f;
                }
            } else {
                float l[3];
#pragma unroll
                for (int rr = 0; rr < 3; rr++) {
                    float uu = u[row * 3 + rr];
                    uu = fminf(fmaxf(uu, 1e-7f), 1.0f - 1e-7f);
                    float inner = fmaxf(-logf(uu), 1e-7f);
                    l[rr] = tv[rr] - logf(inner);      // TAU = 1.0
                }
                float mx = fmaxf(l[0], fmaxf(l[1], l[2]));
                float e0 = expf(l[0] - mx);
                float e1 = expf(l[1] - mx);
                float e2 = expf(l[2] - mx);
                float inv = 1.0f / (e0 + e1 + e2);
#pragma unroll
                for (int rr = 0; rr < 3; rr++)
                    out_idx[row * 3 + rr] = (float)ti[rr];
                out_w[row * 3 + 0] = e0 * inv;
                out_w[row * 3 + 1] = e1 * inv;
                out_w[row * 3 + 2] = e2 * inv;
            }
        }
    }
}

// ---------------------------------------------------------------------------
// Launch: d_out layout = [top_idx (M*3) | weights (M*3) | sim (M*K)]
// ---------------------------------------------------------------------------
extern "C" void kernel_launch(void* const* d_in, const int* in_sizes, int n_in,
                              void* d_out, int out_size)
{
    const float* q     = (const float*)d_in[0];   // [8,4096,256]
    const float* codes = (const float*)d_in[1];   // [1024,256]
    const int*   mask  = (const int*)  d_in[2];   // [8,4096]
    const float* u     = (const float*)d_in[3];   // [8,4096,3]

    float* out      = (float*)d_out;
    float* out_idx  = out;
    float* out_w    = out + (size_t)M_TOTAL * TOPM;
    float* sim      = out + (size_t)2 * M_TOTAL * TOPM;

    vq_zero_cnt_kernel<<<1, MTILES>>>();

    dim3 grid(NCODES / BN, M_TOTAL / BM);   // (8, 256)
    vq_fused_kernel<<<grid, 256>>>(q, codes, sim, mask, u, out_idx, out_w);
}

// round 13
// speedup vs baseline: 1.1799x; 1.1799x over previous
#include <cuda_runtime.h>
#include <math.h>

// Problem constants
#define BATCH   8
#define SEQ     4096
#define M_TOTAL (BATCH * SEQ)   // 32768
#define NCODES  1024
#define KDIM    256
#define TOPM    3

// GEMM tiling
#define BM 128
#define BN 128
#define BK 16
#define NTILES (NCODES / BN)    // 8

// Per-(row, n-tile) max of sim: 32768 x 8 floats = 1 MB scratch
__device__ float g_rowmax[(size_t)M_TOTAL * NTILES];

// ---------------------------------------------------------------------------
// Packed fp32x2 helpers (sm_100 Blackwell dual-lane FP32, bit-exact vs fmaf)
// ---------------------------------------------------------------------------
__device__ __forceinline__ unsigned long long pack2(float x) {
    unsigned long long r;
    asm("mov.b64 %0, {%1, %1};" : "=l"(r) : "f"(x));
    return r;
}
__device__ __forceinline__ void fma2(unsigned long long& acc,
                                     unsigned long long a,
                                     unsigned long long b) {
    asm("fma.rn.f32x2 %0, %1, %2, %0;" : "+l"(acc) : "l"(a), "l"(b));
}
__device__ __forceinline__ float2 unpack2(unsigned long long v) {
    float2 f;
    asm("mov.b64 {%0, %1}, %2;" : "=f"(f.x), "=f"(f.y) : "l"(v));
    return f;
}

// ---------------------------------------------------------------------------
// Kernel 1: sim = q @ codes^T via fma.f32x2 (at the FFMA2 RF-banking roofline)
// BYTE-IDENTICAL to the R11 355us-best GEMM (incl. tiny rowmax epilogue).
// Fusion attempts (R6, R12) both cost ~+90us via register pressure: keep out.
// ---------------------------------------------------------------------------
__global__ __launch_bounds__(256, 2)
void vq_sgemm_kernel(const float* __restrict__ A,    // [M_TOTAL, KDIM]
                     const float* __restrict__ Bm,   // [NCODES,  KDIM]
                     float* __restrict__ C)          // [M_TOTAL, NCODES]
{
    __shared__ float As[BK][BM + 4];   // stride 132 floats
    __shared__ float Bs[BK][BN + 4];

    const int bn0 = blockIdx.x * BN;
    const int bm0 = blockIdx.y * BM;
    const int tid = threadIdx.x;
    const int tx  = tid & 15;          // 0..15 -> N
    const int ty  = tid >> 4;          // 0..15 -> M

    const int lrow0 = tid >> 2;              // 0..63
    const int lrow1 = lrow0 + 64;            // 64..127
    const int lc4   = (tid & 3) * 4;         // 0,4,8,12

    const float* Aptr0 = &A[(size_t)(bm0 + lrow0) * KDIM + lc4];
    const float* Aptr1 = &A[(size_t)(bm0 + lrow1) * KDIM + lc4];
    const float* Bptr0 = &Bm[(size_t)(bn0 + lrow0) * KDIM + lc4];
    const float* Bptr1 = &Bm[(size_t)(bn0 + lrow1) * KDIM + lc4];

    unsigned long long acc2[8][4];
#pragma unroll
    for (int i = 0; i < 8; i++)
#pragma unroll
        for (int j = 0; j < 4; j++) acc2[i][j] = 0ull;

    // Prologue: load chunk 0
    float4 pa0 = *reinterpret_cast<const float4*>(Aptr0);
    float4 pa1 = *reinterpret_cast<const float4*>(Aptr1);
    float4 pb0 = *reinterpret_cast<const float4*>(Bptr0);
    float4 pb1 = *reinterpret_cast<const float4*>(Bptr1);

#pragma unroll 1
    for (int c = 0; c < KDIM / BK; c++) {
        As[lc4 + 0][lrow0] = pa0.x; As[lc4 + 1][lrow0] = pa0.y;
        As[lc4 + 2][lrow0] = pa0.z; As[lc4 + 3][lrow0] = pa0.w;
        As[lc4 + 0][lrow1] = pa1.x; As[lc4 + 1][lrow1] = pa1.y;
        As[lc4 + 2][lrow1] = pa1.z; As[lc4 + 3][lrow1] = pa1.w;
        Bs[lc4 + 0][lrow0] = pb0.x; Bs[lc4 + 1][lrow0] = pb0.y;
        Bs[lc4 + 2][lrow0] = pb0.z; Bs[lc4 + 3][lrow0] = pb0.w;
        Bs[lc4 + 0][lrow1] = pb1.x; Bs[lc4 + 1][lrow1] = pb1.y;
        Bs[lc4 + 2][lrow1] = pb1.z; Bs[lc4 + 3][lrow1] = pb1.w;
        __syncthreads();

        if (c + 1 < KDIM / BK) {
            int koff = (c + 1) * BK;
            pa0 = *reinterpret_cast<const float4*>(Aptr0 + koff);
            pa1 = *reinterpret_cast<const float4*>(Aptr1 + koff);
            pb0 = *reinterpret_cast<const float4*>(Bptr0 + koff);
            pb1 = *reinterpret_cast<const float4*>(Bptr1 + koff);
        }

#pragma unroll
        for (int kk = 0; kk < BK; kk++) {
            float4 a0 = *reinterpret_cast<const float4*>(&As[kk][ty * 4]);
            float4 a1 = *reinterpret_cast<const float4*>(&As[kk][64 + ty * 4]);
            ulonglong2 bp = *reinterpret_cast<const ulonglong2*>(&Bs[kk][tx * 4]);
            ulonglong2 bq = *reinterpret_cast<const ulonglong2*>(&Bs[kk][64 + tx * 4]);

            float av[8] = {a0.x, a0.y, a0.z, a0.w, a1.x, a1.y, a1.z, a1.w};
#pragma unroll
            for (int i = 0; i < 8; i++) {
                unsigned long long ap = pack2(av[i]);
                fma2(acc2[i][0], ap, bp.x);
                fma2(acc2[i][1], ap, bp.y);
                fma2(acc2[i][2], ap, bq.x);
                fma2(acc2[i][3], ap, bq.y);
            }
        }
        __syncthreads();
    }

#pragma unroll
    for (int ih = 0; ih < 2; ih++) {
#pragma unroll
        for (int ii = 0; ii < 4; ii++) {
            int i = ih * 4 + ii;
            int row = bm0 + ih * 64 + ty * 4 + ii;
            float* crow = &C[(size_t)row * NCODES + bn0];
            float2 c0 = unpack2(acc2[i][0]);
            float2 c1 = unpack2(acc2[i][1]);
            float2 c2 = unpack2(acc2[i][2]);
            float2 c3 = unpack2(acc2[i][3]);
            *reinterpret_cast<float4*>(&crow[tx * 4]) =
                make_float4(c0.x, c0.y, c1.x, c1.y);
            *reinterpret_cast<float4*>(&crow[64 + tx * 4]) =
                make_float4(c2.x, c2.y, c3.x, c3.y);

            // Row-tile max for the topk prefilter. Lanes [0..15] / [16..31]
            // hold two distinct rows; xor 1,2,4,8 stays within each group.
            float mrow = fmaxf(fmaxf(fmaxf(c0.x, c0.y), fmaxf(c1.x, c1.y)),
                               fmaxf(fmaxf(c2.x, c2.y), fmaxf(c3.x, c3.y)));
#pragma unroll
            for (int off = 1; off <= 8; off <<= 1)
                mrow = fmaxf(mrow, __shfl_xor_sync(0xffffffffu, mrow, off));
            if (tx == 0)
                g_rowmax[(size_t)row * NTILES + blockIdx.x] = mrow;
        }
    }
}

// ---------------------------------------------------------------------------
// Kernel 2: per-row masked top-3 + Gumbel softmax. One warp per row.
// R13 changes vs R11:
//   (1) mask==0 early-out BEFORE any sim read: masked rows' outputs are
//       fixed (idx 0,1,2 / w 0) and never depend on the scan -> skip ~50%
//       of all sim reads and insert/merge work.
//   (2) reverse row order: GEMM m-tiles complete roughly in ascending order,
//       so the highest rows are freshest in L2 when topk starts.
// Tile-max prefilter (rank<=2 keep, warp-uniform) unchanged from R11.
// ---------------------------------------------------------------------------
__global__ __launch_bounds__(256)
void vq_topk_kernel(const float* __restrict__ sim,   // [M_TOTAL, NCODES]
                    const int*   __restrict__ mask,  // [M_TOTAL]
                    const float* __restrict__ u,     // [M_TOTAL, 3]
                    float* __restrict__ out_idx,     // [M_TOTAL, 3] (as float)
                    float* __restrict__ out_w)       // [M_TOTAL, 3]
{
    const int rid  = blockIdx.x * 8 + (threadIdx.x >> 5);
    const int row  = (M_TOTAL - 1) - rid;             // reverse for L2 reuse
    const int lane = threadIdx.x & 31;

    // (1) Early out for masked rows: outputs are scan-independent.
    const int m = mask[row];                          // warp-uniform load
    if (m == 0) {
        if (lane == 0) {
#pragma unroll
            for (int rr = 0; rr < 3; rr++) {
                out_idx[row * 3 + rr] = (float)rr;
                out_w[row * 3 + rr]   = 0.0f;
            }
        }
        return;                                       // whole warp exits
    }

    const float* srow = sim + (size_t)row * NCODES;

    // --- Tile selection from rowmax (keep: <=2 strictly greater peers) ---
    float x = g_rowmax[(size_t)row * NTILES + (lane & 7)];
    int cnt = 0;
#pragma unroll
    for (int j = 0; j < 8; j++) {
        float xj = __shfl_sync(0xffffffffu, x, j);
        cnt += (xj > x) ? 1 : 0;
    }
    unsigned keep = __ballot_sync(0xffffffffu, cnt <= 2) & 0xffu;  // bits 0..7

    const float NEG_INF = -__int_as_float(0x7f800000);  // -inf
    float v0 = NEG_INF, v1 = NEG_INF, v2 = NEG_INF;
    int   i0 = 0x7fffffff, i1 = 0x7fffffff, i2 = 0x7fffffff;

    // Within-lane index order is strictly increasing inside each tile, and
    // tiles are visited in ascending order, so strict '>' keeps the smaller
    // index on ties.
#pragma unroll
    for (int t = 0; t < NTILES; t++) {
        if (keep & (1u << t)) {    // warp-uniform branch
            int base = t * 128 + lane * 4;
            float4 v4 = *reinterpret_cast<const float4*>(&srow[base]);
            float vv[4] = {v4.x, v4.y, v4.z, v4.w};
#pragma unroll
            for (int e = 0; e < 4; e++) {
                float v = vv[e];
                int idx = base + e;
                if (v > v0)      { v2 = v1; i2 = i1; v1 = v0; i1 = i0; v0 = v; i0 = idx; }
                else if (v > v1) { v2 = v1; i2 = i1; v1 = v;  i1 = idx; }
                else if (v > v2) { v2 = v;  i2 = idx; }
            }
        }
    }

    // Warp merge: 3 rounds of (value, index) arg-max with smaller-index
    // tie-break. Each lane keeps a cursor into its sorted local top-3.
    float lv[3] = {v0, v1, v2};
    int   li[3] = {i0, i1, i2};
    float tv[3];
    int   ti[3];
    int p = 0;
#pragma unroll
    for (int rr = 0; rr < 3; rr++) {
        float bv = (p < 3) ? lv[p] : NEG_INF;
        int   bi = (p < 3) ? li[p] : 0x7fffffff;
#pragma unroll
        for (int off = 16; off > 0; off >>= 1) {
            float ov = __shfl_xor_sync(0xffffffffu, bv, off);
            int   oi = __shfl_xor_sync(0xffffffffu, bi, off);
            if (ov > bv || (ov == bv && oi < bi)) { bv = ov; bi = oi; }
        }
        tv[rr] = bv; ti[rr] = bi;
        if (p < 3 && li[p] == bi) p++;   // winner lane advances its cursor
    }

    if (lane == 0) {
        float l[3];
#pragma unroll
        for (int rr = 0; rr < 3; rr++) {
            float uu = u[row * 3 + rr];
            uu = fminf(fmaxf(uu, 1e-7f), 1.0f - 1e-7f);
            float inner = fmaxf(-logf(uu), 1e-7f);
            float g = -logf(inner);
            l[rr] = tv[rr] + g;          // TAU = 1.0
        }
        float mx = fmaxf(l[0], fmaxf(l[1], l[2]));
        float e0 = expf(l[0] - mx);
        float e1 = expf(l[1] - mx);
        float e2 = expf(l[2] - mx);
        float inv = 1.0f / (e0 + e1 + e2);
#pragma unroll
        for (int rr = 0; rr < 3; rr++) {
            out_idx[row * 3 + rr] = (float)ti[rr];
        }
        out_w[row * 3 + 0] = e0 * inv;
        out_w[row * 3 + 1] = e1 * inv;
        out_w[row * 3 + 2] = e2 * inv;
    }
}

// ---------------------------------------------------------------------------
// Launch: d_out layout = [top_idx (B*N*3) | weights (B*N*3) | sim (B*N*K)]
// ---------------------------------------------------------------------------
extern "C" void kernel_launch(void* const* d_in, const int* in_sizes, int n_in,
                              void* d_out, int out_size)
{
    const float* q     = (const float*)d_in[0];   // [8,4096,256]
    const float* codes = (const float*)d_in[1];   // [1024,256]
    const int*   mask  = (const int*)  d_in[2];   // [8,4096]
    const float* u     = (const float*)d_in[3];   // [8,4096,3]

    float* out      = (float*)d_out;
    float* out_idx  = out;
    float* out_w    = out + (size_t)M_TOTAL * TOPM;
    float* sim      = out + (size_t)2 * M_TOTAL * TOPM;

    dim3 grid(NCODES / BN, M_TOTAL / BM);
    vq_sgemm_kernel<<<grid, 256>>>(q, codes, sim);

    vq_topk_kernel<<<M_TOTAL / 8, 256>>>(sim, mask, u, out_idx, out_w);
}

// round 14
// speedup vs baseline: 1.1855x; 1.0047x over previous
#include <cuda_runtime.h>
#include <math.h>

// Problem constants
#define BATCH   8
#define SEQ     4096
#define M_TOTAL (BATCH * SEQ)   // 32768
#define NCODES  1024
#define KDIM    256
#define TOPM    3

// GEMM tiling
#define BM 128
#define BN 128
#define BK 16
#define NTILES (NCODES / BN)    // 8

// Per-(row, n-tile) max of sim: 32768 x 8 floats = 1 MB scratch
__device__ float g_rowmax[(size_t)M_TOTAL * NTILES];

// ---------------------------------------------------------------------------
// Packed fp32x2 helpers (sm_100 Blackwell dual-lane FP32, bit-exact vs fmaf)
// ---------------------------------------------------------------------------
__device__ __forceinline__ unsigned long long pack2(float x) {
    unsigned long long r;
    asm("mov.b64 %0, {%1, %1};" : "=l"(r) : "f"(x));
    return r;
}
__device__ __forceinline__ void fma2(unsigned long long& acc,
                                     unsigned long long a,
                                     unsigned long long b) {
    asm("fma.rn.f32x2 %0, %1, %2, %0;" : "+l"(acc) : "l"(a), "l"(b));
}
__device__ __forceinline__ float2 unpack2(unsigned long long v) {
    float2 f;
    asm("mov.b64 {%0, %1}, %2;" : "=f"(f.x), "=f"(f.y) : "l"(v));
    return f;
}

// ---------------------------------------------------------------------------
// Kernel 1: sim = q @ codes^T via fma.f32x2 (at the FFMA2 RF-banking roofline)
// BYTE-IDENTICAL to the R11/R13 GEMM (incl. tiny rowmax epilogue).
// Fusion attempts (R6, R12) both cost ~+90us via register pressure: keep out.
// ---------------------------------------------------------------------------
__global__ __launch_bounds__(256, 2)
void vq_sgemm_kernel(const float* __restrict__ A,    // [M_TOTAL, KDIM]
                     const float* __restrict__ Bm,   // [NCODES,  KDIM]
                     float* __restrict__ C)          // [M_TOTAL, NCODES]
{
    __shared__ float As[BK][BM + 4];   // stride 132 floats
    __shared__ float Bs[BK][BN + 4];

    const int bn0 = blockIdx.x * BN;
    const int bm0 = blockIdx.y * BM;
    const int tid = threadIdx.x;
    const int tx  = tid & 15;          // 0..15 -> N
    const int ty  = tid >> 4;          // 0..15 -> M

    const int lrow0 = tid >> 2;              // 0..63
    const int lrow1 = lrow0 + 64;            // 64..127
    const int lc4   = (tid & 3) * 4;         // 0,4,8,12

    const float* Aptr0 = &A[(size_t)(bm0 + lrow0) * KDIM + lc4];
    const float* Aptr1 = &A[(size_t)(bm0 + lrow1) * KDIM + lc4];
    const float* Bptr0 = &Bm[(size_t)(bn0 + lrow0) * KDIM + lc4];
    const float* Bptr1 = &Bm[(size_t)(bn0 + lrow1) * KDIM + lc4];

    unsigned long long acc2[8][4];
#pragma unroll
    for (int i = 0; i < 8; i++)
#pragma unroll
        for (int j = 0; j < 4; j++) acc2[i][j] = 0ull;

    // Prologue: load chunk 0
    float4 pa0 = *reinterpret_cast<const float4*>(Aptr0);
    float4 pa1 = *reinterpret_cast<const float4*>(Aptr1);
    float4 pb0 = *reinterpret_cast<const float4*>(Bptr0);
    float4 pb1 = *reinterpret_cast<const float4*>(Bptr1);

#pragma unroll 1
    for (int c = 0; c < KDIM / BK; c++) {
        As[lc4 + 0][lrow0] = pa0.x; As[lc4 + 1][lrow0] = pa0.y;
        As[lc4 + 2][lrow0] = pa0.z; As[lc4 + 3][lrow0] = pa0.w;
        As[lc4 + 0][lrow1] = pa1.x; As[lc4 + 1][lrow1] = pa1.y;
        As[lc4 + 2][lrow1] = pa1.z; As[lc4 + 3][lrow1] = pa1.w;
        Bs[lc4 + 0][lrow0] = pb0.x; Bs[lc4 + 1][lrow0] = pb0.y;
        Bs[lc4 + 2][lrow0] = pb0.z; Bs[lc4 + 3][lrow0] = pb0.w;
        Bs[lc4 + 0][lrow1] = pb1.x; Bs[lc4 + 1][lrow1] = pb1.y;
        Bs[lc4 + 2][lrow1] = pb1.z; Bs[lc4 + 3][lrow1] = pb1.w;
        __syncthreads();

        if (c + 1 < KDIM / BK) {
            int koff = (c + 1) * BK;
            pa0 = *reinterpret_cast<const float4*>(Aptr0 + koff);
            pa1 = *reinterpret_cast<const float4*>(Aptr1 + koff);
            pb0 = *reinterpret_cast<const float4*>(Bptr0 + koff);
            pb1 = *reinterpret_cast<const float4*>(Bptr1 + koff);
        }

#pragma unroll
        for (int kk = 0; kk < BK; kk++) {
            float4 a0 = *reinterpret_cast<const float4*>(&As[kk][ty * 4]);
            float4 a1 = *reinterpret_cast<const float4*>(&As[kk][64 + ty * 4]);
            ulonglong2 bp = *reinterpret_cast<const ulonglong2*>(&Bs[kk][tx * 4]);
            ulonglong2 bq = *reinterpret_cast<const ulonglong2*>(&Bs[kk][64 + tx * 4]);

            float av[8] = {a0.x, a0.y, a0.z, a0.w, a1.x, a1.y, a1.z, a1.w};
#pragma unroll
            for (int i = 0; i < 8; i++) {
                unsigned long long ap = pack2(av[i]);
                fma2(acc2[i][0], ap, bp.x);
                fma2(acc2[i][1], ap, bp.y);
                fma2(acc2[i][2], ap, bq.x);
                fma2(acc2[i][3], ap, bq.y);
            }
        }
        __syncthreads();
    }

#pragma unroll
    for (int ih = 0; ih < 2; ih++) {
#pragma unroll
        for (int ii = 0; ii < 4; ii++) {
            int i = ih * 4 + ii;
            int row = bm0 + ih * 64 + ty * 4 + ii;
            float* crow = &C[(size_t)row * NCODES + bn0];
            float2 c0 = unpack2(acc2[i][0]);
            float2 c1 = unpack2(acc2[i][1]);
            float2 c2 = unpack2(acc2[i][2]);
            float2 c3 = unpack2(acc2[i][3]);
            *reinterpret_cast<float4*>(&crow[tx * 4]) =
                make_float4(c0.x, c0.y, c1.x, c1.y);
            *reinterpret_cast<float4*>(&crow[64 + tx * 4]) =
                make_float4(c2.x, c2.y, c3.x, c3.y);

            // Row-tile max for the topk prefilter. Lanes [0..15] / [16..31]
            // hold two distinct rows; xor 1,2,4,8 stays within each group.
            float mrow = fmaxf(fmaxf(fmaxf(c0.x, c0.y), fmaxf(c1.x, c1.y)),
                               fmaxf(fmaxf(c2.x, c2.y), fmaxf(c3.x, c3.y)));
#pragma unroll
            for (int off = 1; off <= 8; off <<= 1)
                mrow = fmaxf(mrow, __shfl_xor_sync(0xffffffffu, mrow, off));
            if (tx == 0)
                g_rowmax[(size_t)row * NTILES + blockIdx.x] = mrow;
        }
    }
}

// ---------------------------------------------------------------------------
// Kernel 2: per-row masked top-3 + Gumbel softmax. One warp per row.
// R14 changes vs R13:
//   (1) mask and rowmax loads issued TOGETHER before the early-exit branch
//       (independent loads; removes one serialized memory round-trip from
//       the warp's critical path).
//   (2) block 256 -> 128 (4 warps): finished blocks retire sooner and are
//       backfilled, shrinking the masked-warp imbalance tail.
// Mask early-out, reverse row order, rank<=2 tile prefilter: unchanged.
// ---------------------------------------------------------------------------
__global__ __launch_bounds__(128)
void vq_topk_kernel(const float* __restrict__ sim,   // [M_TOTAL, NCODES]
                    const int*   __restrict__ mask,  // [M_TOTAL]
                    const float* __restrict__ u,     // [M_TOTAL, 3]
                    float* __restrict__ out_idx,     // [M_TOTAL, 3] (as float)
                    float* __restrict__ out_w)       // [M_TOTAL, 3]
{
    const int rid  = blockIdx.x * 4 + (threadIdx.x >> 5);
    const int row  = (M_TOTAL - 1) - rid;             // reverse for L2 reuse
    const int lane = threadIdx.x & 31;

    // Issue BOTH independent loads before any branch.
    const int   m = mask[row];                        // warp-uniform
    const float x = g_rowmax[(size_t)row * NTILES + (lane & 7)];

    // Early out for masked rows: outputs are scan-independent.
    if (m == 0) {
        if (lane == 0) {
#pragma unroll
            for (int rr = 0; rr < 3; rr++) {
                out_idx[row * 3 + rr] = (float)rr;
                out_w[row * 3 + rr]   = 0.0f;
            }
        }
        return;                                       // whole warp exits
    }

    const float* srow = sim + (size_t)row * NCODES;

    // --- Tile selection from rowmax (keep: <=2 strictly greater peers) ---
    int cnt = 0;
#pragma unroll
    for (int j = 0; j < 8; j++) {
        float xj = __shfl_sync(0xffffffffu, x, j);
        cnt += (xj > x) ? 1 : 0;
    }
    unsigned keep = __ballot_sync(0xffffffffu, cnt <= 2) & 0xffu;  // bits 0..7

    const float NEG_INF = -__int_as_float(0x7f800000);  // -inf
    float v0 = NEG_INF, v1 = NEG_INF, v2 = NEG_INF;
    int   i0 = 0x7fffffff, i1 = 0x7fffffff, i2 = 0x7fffffff;

    // Within-lane index order is strictly increasing inside each tile, and
    // tiles are visited in ascending order, so strict '>' keeps the smaller
    // index on ties.
#pragma unroll
    for (int t = 0; t < NTILES; t++) {
        if (keep & (1u << t)) {    // warp-uniform branch
            int base = t * 128 + lane * 4;
            float4 v4 = *reinterpret_cast<const float4*>(&srow[base]);
            float vv[4] = {v4.x, v4.y, v4.z, v4.w};
#pragma unroll
            for (int e = 0; e < 4; e++) {
                float v = vv[e];
                int idx = base + e;
                if (v > v0)      { v2 = v1; i2 = i1; v1 = v0; i1 = i0; v0 = v; i0 = idx; }
                else if (v > v1) { v2 = v1; i2 = i1; v1 = v;  i1 = idx; }
                else if (v > v2) { v2 = v;  i2 = idx; }
            }
        }
    }

    // Warp merge: 3 rounds of (value, index) arg-max with smaller-index
    // tie-break. Each lane keeps a cursor into its sorted local top-3.
    float lv[3] = {v0, v1, v2};
    int   li[3] = {i0, i1, i2};
    float tv[3];
    int   ti[3];
    int p = 0;
#pragma unroll
    for (int rr = 0; rr < 3; rr++) {
        float bv = (p < 3) ? lv[p] : NEG_INF;
        int   bi = (p < 3) ? li[p] : 0x7fffffff;
#pragma unroll
        for (int off = 16; off > 0; off >>= 1) {
            float ov = __shfl_xor_sync(0xffffffffu, bv, off);
            int   oi = __shfl_xor_sync(0xffffffffu, bi, off);
            if (ov > bv || (ov == bv && oi < bi)) { bv = ov; bi = oi; }
        }
        tv[rr] = bv; ti[rr] = bi;
        if (p < 3 && li[p] == bi) p++;   // winner lane advances its cursor
    }

    if (lane == 0) {
        float l[3];
#pragma unroll
        for (int rr = 0; rr < 3; rr++) {
            float uu = u[row * 3 + rr];
            uu = fminf(fmaxf(uu, 1e-7f), 1.0f - 1e-7f);
            float inner = fmaxf(-logf(uu), 1e-7f);
            float g = -logf(inner);
            l[rr] = tv[rr] + g;          // TAU = 1.0
        }
        float mx = fmaxf(l[0], fmaxf(l[1], l[2]));
        float e0 = expf(l[0] - mx);
        float e1 = expf(l[1] - mx);
        float e2 = expf(l[2] - mx);
        float inv = 1.0f / (e0 + e1 + e2);
#pragma unroll
        for (int rr = 0; rr < 3; rr++) {
            out_idx[row * 3 + rr] = (float)ti[rr];
        }
        out_w[row * 3 + 0] = e0 * inv;
        out_w[row * 3 + 1] = e1 * inv;
        out_w[row * 3 + 2] = e2 * inv;
    }
}

// ---------------------------------------------------------------------------
// Launch: d_out layout = [top_idx (B*N*3) | weights (B*N*3) | sim (B*N*K)]
// ---------------------------------------------------------------------------
extern "C" void kernel_launch(void* const* d_in, const int* in_sizes, int n_in,
                              void* d_out, int out_size)
{
    const float* q     = (const float*)d_in[0];   // [8,4096,256]
    const float* codes = (const float*)d_in[1];   // [1024,256]
    const int*   mask  = (const int*)  d_in[2];   // [8,4096]
    const float* u     = (const float*)d_in[3];   // [8,4096,3]

    float* out      = (float*)d_out;
    float* out_idx  = out;
    float* out_w    = out + (size_t)M_TOTAL * TOPM;
    float* sim      = out + (size_t)2 * M_TOTAL * TOPM;

    dim3 grid(NCODES / BN, M_TOTAL / BM);
    vq_sgemm_kernel<<<grid, 256>>>(q, codes, sim);

    vq_topk_kernel<<<M_TOTAL / 4, 128>>>(sim, mask, u, out_idx, out_w);
}

// round 15
// speedup vs baseline: 1.1861x; 1.0005x over previous
#include <cuda_runtime.h>
#include <math.h>

// Problem constants
#define BATCH   8
#define SEQ     4096
#define M_TOTAL (BATCH * SEQ)   // 32768
#define NCODES  1024
#define KDIM    256
#define TOPM    3

// GEMM tiling
#define BM 128
#define BN 128
#define BK 16
#define NTILES (NCODES / BN)    // 8

// Per-(row, n-tile) max of sim: 32768 x 8 floats = 1 MB scratch
__device__ float g_rowmax[(size_t)M_TOTAL * NTILES];

// ---------------------------------------------------------------------------
// Packed fp32x2 helpers (sm_100 Blackwell dual-lane FP32, bit-exact vs fmaf)
// ---------------------------------------------------------------------------
__device__ __forceinline__ unsigned long long pack2(float x) {
    unsigned long long r;
    asm("mov.b64 %0, {%1, %1};" : "=l"(r) : "f"(x));
    return r;
}
__device__ __forceinline__ void fma2(unsigned long long& acc,
                                     unsigned long long a,
                                     unsigned long long b) {
    asm("fma.rn.f32x2 %0, %1, %2, %0;" : "+l"(acc) : "l"(a), "l"(b));
}
__device__ __forceinline__ float2 unpack2(unsigned long long v) {
    float2 f;
    asm("mov.b64 {%0, %1}, %2;" : "=f"(f.x), "=f"(f.y) : "l"(v));
    return f;
}

// ---------------------------------------------------------------------------
// Kernel 1: sim = q @ codes^T via fma.f32x2 (at the FFMA2 RF-banking roofline)
// BYTE-IDENTICAL to the R11/R13/R14 GEMM (incl. tiny rowmax epilogue).
// Fusion attempts (R6, R12) both cost ~+90us via register pressure: keep out.
// ---------------------------------------------------------------------------
__global__ __launch_bounds__(256, 2)
void vq_sgemm_kernel(const float* __restrict__ A,    // [M_TOTAL, KDIM]
                     const float* __restrict__ Bm,   // [NCODES,  KDIM]
                     float* __restrict__ C)          // [M_TOTAL, NCODES]
{
    __shared__ float As[BK][BM + 4];   // stride 132 floats
    __shared__ float Bs[BK][BN + 4];

    const int bn0 = blockIdx.x * BN;
    const int bm0 = blockIdx.y * BM;
    const int tid = threadIdx.x;
    const int tx  = tid & 15;          // 0..15 -> N
    const int ty  = tid >> 4;          // 0..15 -> M

    const int lrow0 = tid >> 2;              // 0..63
    const int lrow1 = lrow0 + 64;            // 64..127
    const int lc4   = (tid & 3) * 4;         // 0,4,8,12

    const float* Aptr0 = &A[(size_t)(bm0 + lrow0) * KDIM + lc4];
    const float* Aptr1 = &A[(size_t)(bm0 + lrow1) * KDIM + lc4];
    const float* Bptr0 = &Bm[(size_t)(bn0 + lrow0) * KDIM + lc4];
    const float* Bptr1 = &Bm[(size_t)(bn0 + lrow1) * KDIM + lc4];

    unsigned long long acc2[8][4];
#pragma unroll
    for (int i = 0; i < 8; i++)
#pragma unroll
        for (int j = 0; j < 4; j++) acc2[i][j] = 0ull;

    // Prologue: load chunk 0
    float4 pa0 = *reinterpret_cast<const float4*>(Aptr0);
    float4 pa1 = *reinterpret_cast<const float4*>(Aptr1);
    float4 pb0 = *reinterpret_cast<const float4*>(Bptr0);
    float4 pb1 = *reinterpret_cast<const float4*>(Bptr1);

#pragma unroll 1
    for (int c = 0; c < KDIM / BK; c++) {
        As[lc4 + 0][lrow0] = pa0.x; As[lc4 + 1][lrow0] = pa0.y;
        As[lc4 + 2][lrow0] = pa0.z; As[lc4 + 3][lrow0] = pa0.w;
        As[lc4 + 0][lrow1] = pa1.x; As[lc4 + 1][lrow1] = pa1.y;
        As[lc4 + 2][lrow1] = pa1.z; As[lc4 + 3][lrow1] = pa1.w;
        Bs[lc4 + 0][lrow0] = pb0.x; Bs[lc4 + 1][lrow0] = pb0.y;
        Bs[lc4 + 2][lrow0] = pb0.z; Bs[lc4 + 3][lrow0] = pb0.w;
        Bs[lc4 + 0][lrow1] = pb1.x; Bs[lc4 + 1][lrow1] = pb1.y;
        Bs[lc4 + 2][lrow1] = pb1.z; Bs[lc4 + 3][lrow1] = pb1.w;
        __syncthreads();

        if (c + 1 < KDIM / BK) {
            int koff = (c + 1) * BK;
            pa0 = *reinterpret_cast<const float4*>(Aptr0 + koff);
            pa1 = *reinterpret_cast<const float4*>(Aptr1 + koff);
            pb0 = *reinterpret_cast<const float4*>(Bptr0 + koff);
            pb1 = *reinterpret_cast<const float4*>(Bptr1 + koff);
        }

#pragma unroll
        for (int kk = 0; kk < BK; kk++) {
            float4 a0 = *reinterpret_cast<const float4*>(&As[kk][ty * 4]);
            float4 a1 = *reinterpret_cast<const float4*>(&As[kk][64 + ty * 4]);
            ulonglong2 bp = *reinterpret_cast<const ulonglong2*>(&Bs[kk][tx * 4]);
            ulonglong2 bq = *reinterpret_cast<const ulonglong2*>(&Bs[kk][64 + tx * 4]);

            float av[8] = {a0.x, a0.y, a0.z, a0.w, a1.x, a1.y, a1.z, a1.w};
#pragma unroll
            for (int i = 0; i < 8; i++) {
                unsigned long long ap = pack2(av[i]);
                fma2(acc2[i][0], ap, bp.x);
                fma2(acc2[i][1], ap, bp.y);
                fma2(acc2[i][2], ap, bq.x);
                fma2(acc2[i][3], ap, bq.y);
            }
        }
        __syncthreads();
    }

#pragma unroll
    for (int ih = 0; ih < 2; ih++) {
#pragma unroll
        for (int ii = 0; ii < 4; ii++) {
            int i = ih * 4 + ii;
            int row = bm0 + ih * 64 + ty * 4 + ii;
            float* crow = &C[(size_t)row * NCODES + bn0];
            float2 c0 = unpack2(acc2[i][0]);
            float2 c1 = unpack2(acc2[i][1]);
            float2 c2 = unpack2(acc2[i][2]);
            float2 c3 = unpack2(acc2[i][3]);
            *reinterpret_cast<float4*>(&crow[tx * 4]) =
                make_float4(c0.x, c0.y, c1.x, c1.y);
            *reinterpret_cast<float4*>(&crow[64 + tx * 4]) =
                make_float4(c2.x, c2.y, c3.x, c3.y);

            // Row-tile max for the topk prefilter. Lanes [0..15] / [16..31]
            // hold two distinct rows; xor 1,2,4,8 stays within each group.
            float mrow = fmaxf(fmaxf(fmaxf(c0.x, c0.y), fmaxf(c1.x, c1.y)),
                               fmaxf(fmaxf(c2.x, c2.y), fmaxf(c3.x, c3.y)));
#pragma unroll
            for (int off = 1; off <= 8; off <<= 1)
                mrow = fmaxf(mrow, __shfl_xor_sync(0xffffffffu, mrow, off));
            if (tx == 0)
                g_rowmax[(size_t)row * NTILES + blockIdx.x] = mrow;
        }
    }
}

// ---------------------------------------------------------------------------
// Kernel 2: per-row masked top-3 + Gumbel softmax. One warp per row.
// R15 changes vs R14:
//   (1) EXACT-3 tile selection via lexicographic rank (max desc, tile asc):
//       ranks are distinct -> exactly 3 kept tiles, extracted as uniform
//       indices -> straight-line code, 3 sim loads batched (MLP 3) instead
//       of branch-serialized (MLP 1). Provably identical selection.
//   (2) Gumbel (u-load + logf chain) hoisted before the sim loads are
//       consumed: MUFU latency hides under the memory wait.
// Mask early-out, reverse row order: unchanged.
// ---------------------------------------------------------------------------
__global__ __launch_bounds__(128)
void vq_topk_kernel(const float* __restrict__ sim,   // [M_TOTAL, NCODES]
                    const int*   __restrict__ mask,  // [M_TOTAL]
                    const float* __restrict__ u,     // [M_TOTAL, 3]
                    float* __restrict__ out_idx,     // [M_TOTAL, 3] (as float)
                    float* __restrict__ out_w)       // [M_TOTAL, 3]
{
    const int rid  = blockIdx.x * 4 + (threadIdx.x >> 5);
    const int row  = (M_TOTAL - 1) - rid;             // reverse for L2 reuse
    const int lane = threadIdx.x & 31;
    const int tl   = lane & 7;

    // Issue both independent loads before any branch.
    const int   m = mask[row];                        // warp-uniform
    const float x = g_rowmax[(size_t)row * NTILES + tl];

    // Early out for masked rows: outputs are scan-independent.
    if (m == 0) {
        if (lane == 0) {
#pragma unroll
            for (int rr = 0; rr < 3; rr++) {
                out_idx[row * 3 + rr] = (float)rr;
                out_w[row * 3 + rr]   = 0.0f;
            }
        }
        return;                                       // whole warp exits
    }

    // --- Exact-3 tile selection: lexicographic rank (value desc, tile asc).
    // Ranks are distinct, so exactly 3 lanes (among 0..7) have rank <= 2.
    int cnt = 0;
#pragma unroll
    for (int j = 0; j < 8; j++) {
        float xj = __shfl_sync(0xffffffffu, x, j);
        cnt += ((xj > x) || (xj == x && j < tl)) ? 1 : 0;
    }
    unsigned keep = __ballot_sync(0xffffffffu, cnt <= 2) & 0xffu;  // 3 bits
    const int t0 = __ffs(keep) - 1;  keep &= keep - 1;             // ascending
    const int t1 = __ffs(keep) - 1;  keep &= keep - 1;
    const int t2 = __ffs(keep) - 1;

    // --- Batched loads of the 3 kept tiles (independent -> MLP 3) ---
    const float* srow = sim + (size_t)row * NCODES;
    const int b0 = t0 * 128 + lane * 4;
    const int b1 = t1 * 128 + lane * 4;
    const int b2 = t2 * 128 + lane * 4;
    const float4 va = *reinterpret_cast<const float4*>(&srow[b0]);
    const float4 vb = *reinterpret_cast<const float4*>(&srow[b1]);
    const float4 vc = *reinterpret_cast<const float4*>(&srow[b2]);

    // --- Gumbel hoist (scan-independent): hides u-load + logf latency
    // under the outstanding sim loads.
    float g0 = 0.0f, g1 = 0.0f, g2 = 0.0f;
    if (lane == 0) {
        float u0 = u[row * 3 + 0];
        float u1 = u[row * 3 + 1];
        float u2 = u[row * 3 + 2];
        u0 = fminf(fmaxf(u0, 1e-7f), 1.0f - 1e-7f);
        u1 = fminf(fmaxf(u1, 1e-7f), 1.0f - 1e-7f);
        u2 = fminf(fmaxf(u2, 1e-7f), 1.0f - 1e-7f);
        g0 = -logf(fmaxf(-logf(u0), 1e-7f));
        g1 = -logf(fmaxf(-logf(u1), 1e-7f));
        g2 = -logf(fmaxf(-logf(u2), 1e-7f));
    }

    const float NEG_INF = -__int_as_float(0x7f800000);  // -inf
    float v0 = NEG_INF, v1 = NEG_INF, v2 = NEG_INF;
    int   i0 = 0x7fffffff, i1 = 0x7fffffff, i2 = 0x7fffffff;

    // Insert chains: tiles in ascending column order (t0 < t1 < t2), within
    // each tile indices ascend -> strict '>' keeps the smaller index on ties.
    {
        float vv[12] = {va.x, va.y, va.z, va.w,
                        vb.x, vb.y, vb.z, vb.w,
                        vc.x, vc.y, vc.z, vc.w};
        int   bb[3]  = {b0, b1, b2};
#pragma unroll
        for (int t = 0; t < 3; t++) {
#pragma unroll
            for (int e = 0; e < 4; e++) {
                float v = vv[t * 4 + e];
                int idx = bb[t] + e;
                if (v > v0)      { v2 = v1; i2 = i1; v1 = v0; i1 = i0; v0 = v; i0 = idx; }
                else if (v > v1) { v2 = v1; i2 = i1; v1 = v;  i1 = idx; }
                else if (v > v2) { v2 = v;  i2 = idx; }
            }
        }
    }

    // Warp merge: 3 rounds of (value, index) arg-max with smaller-index
    // tie-break. Each lane keeps a cursor into its sorted local top-3.
    float lv[3] = {v0, v1, v2};
    int   li[3] = {i0, i1, i2};
    float tv[3];
    int   ti[3];
    int p = 0;
#pragma unroll
    for (int rr = 0; rr < 3; rr++) {
        float bv = (p < 3) ? lv[p] : NEG_INF;
        int   bi = (p < 3) ? li[p] : 0x7fffffff;
#pragma unroll
        for (int off = 16; off > 0; off >>= 1) {
            float ov = __shfl_xor_sync(0xffffffffu, bv, off);
            int   oi = __shfl_xor_sync(0xffffffffu, bi, off);
            if (ov > bv || (ov == bv && oi < bi)) { bv = ov; bi = oi; }
        }
        tv[rr] = bv; ti[rr] = bi;
        if (p < 3 && li[p] == bi) p++;   // winner lane advances its cursor
    }

    if (lane == 0) {
        float l0 = tv[0] + g0;           // TAU = 1.0
        float l1 = tv[1] + g1;
        float l2 = tv[2] + g2;
        float mx = fmaxf(l0, fmaxf(l1, l2));
        float e0 = expf(l0 - mx);
        float e1 = expf(l1 - mx);
        float e2 = expf(l2 - mx);
        float inv = 1.0f / (e0 + e1 + e2);
#pragma unroll
        for (int rr = 0; rr < 3; rr++) {
            out_idx[row * 3 + rr] = (float)ti[rr];
        }
        out_w[row * 3 + 0] = e0 * inv;
        out_w[row * 3 + 1] = e1 * inv;
        out_w[row * 3 + 2] = e2 * inv;
    }
}

// ---------------------------------------------------------------------------
// Launch: d_out layout = [top_idx (B*N*3) | weights (B*N*3) | sim (B*N*K)]
// ---------------------------------------------------------------------------
extern "C" void kernel_launch(void* const* d_in, const int* in_sizes, int n_in,
                              void* d_out, int out_size)
{
    const float* q     = (const float*)d_in[0];   // [8,4096,256]
    const float* codes = (const float*)d_in[1];   // [1024,256]
    const int*   mask  = (const int*)  d_in[2];   // [8,4096]
    const float* u     = (const float*)d_in[3];   // [8,4096,3]

    float* out      = (float*)d_out;
    float* out_idx  = out;
    float* out_w    = out + (size_t)M_TOTAL * TOPM;
    float* sim      = out + (size_t)2 * M_TOTAL * TOPM;

    dim3 grid(NCODES / BN, M_TOTAL / BM);
    vq_sgemm_kernel<<<grid, 256>>>(q, codes, sim);

    vq_topk_kernel<<<M_TOTAL / 4, 128>>>(sim, mask, u, out_idx, out_w);
}